// round 1
// baseline (speedup 1.0000x reference)
#include <cuda_runtime.h>
#include <cstdint>

#define N_MAX 4096
#define FULLMASK 0xFFFFFFFFu

// Scratch (no allocations allowed): packed positions + per-row counts/offsets.
__device__ float4 g_pos4[N_MAX];
__device__ int    g_count[N_MAX];
__device__ int    g_offset[N_MAX];

// Pack pos (N,3) + batch into float4 {x,y,z,batch_bits} for single LDG.128 per pair eval.
__global__ void pack_kernel(const float* __restrict__ pos,
                            const int* __restrict__ batch, int n) {
    int i = blockIdx.x * blockDim.x + threadIdx.x;
    if (i < n) {
        float4 p;
        p.x = pos[3 * i + 0];
        p.y = pos[3 * i + 1];
        p.z = pos[3 * i + 2];
        p.w = __int_as_float(batch[i]);
        g_pos4[i] = p;
    }
}

// Initialize full output: edge_index region = -1, weight/vec regions = 0.
// float4 stores; 2*mp is a multiple of 4 so no vector straddles the boundary.
__global__ void init_kernel(float* __restrict__ out, int mp) {
    long long idx = (long long)(blockIdx.x * (long long)blockDim.x + threadIdx.x) * 4;
    long long total = 6LL * mp;
    if (idx < total) {
        float v = (idx < 2LL * mp) ? -1.0f : 0.0f;
        *reinterpret_cast<float4*>(out + idx) = make_float4(v, v, v, v);
    }
}

__device__ __forceinline__ bool pair_pred(const float4& pi, const float4& pj,
                                          int i, int j, int n,
                                          float& dx, float& dy, float& dz, float& d2) {
    dx = __fadd_rn(pi.x, -pj.x);
    dy = __fadd_rn(pi.y, -pj.y);
    dz = __fadd_rn(pi.z, -pj.z);
    // Match XLA: round products, then ((xx+yy)+zz), no FMA contraction.
    d2 = __fadd_rn(__fadd_rn(__fmul_rn(dx, dx), __fmul_rn(dy, dy)), __fmul_rn(dz, dz));
    bool pred = (j < n) & (j != i) &
                (__float_as_int(pi.w) == __float_as_int(pj.w)) &
                (d2 < 25.0f);
    if (pred) pred = (__fsqrt_rn(d2) < 5.0f);  // rare path: exact borderline semantics
    return pred;
}

// One warp per row i: count neighbors (j ascending, chunks of 32).
__global__ void count_kernel(int n) {
    int warp = (blockIdx.x * blockDim.x + threadIdx.x) >> 5;
    int lane = threadIdx.x & 31;
    if (warp >= n) return;
    float4 pi = g_pos4[warp];
    int cnt = 0;
    for (int j0 = 0; j0 < n; j0 += 32) {
        int j = j0 + lane;
        float4 pj = g_pos4[j < n ? j : 0];
        float dx, dy, dz, d2;
        bool pred = pair_pred(pi, pj, warp, j, n, dx, dy, dz, d2);
        unsigned m = __ballot_sync(FULLMASK, pred);
        cnt += __popc(m);
    }
    if (lane == 0) g_count[warp] = cnt;
}

// Single-block exclusive scan over up to 4096 counts (1024 threads x 4 items).
__global__ void scan_kernel(int n) {
    __shared__ int sh[1024];
    int t = threadIdx.x;
    int loc[4];
    int sum = 0;
#pragma unroll
    for (int k = 0; k < 4; k++) {
        int idx = t * 4 + k;
        int c = (idx < n) ? g_count[idx] : 0;
        loc[k] = sum;
        sum += c;
    }
    sh[t] = sum;
    __syncthreads();
    // Hillis-Steele inclusive scan over 1024 partials.
    for (int off = 1; off < 1024; off <<= 1) {
        int v = (t >= off) ? sh[t - off] : 0;
        __syncthreads();
        sh[t] += v;
        __syncthreads();
    }
    int base = (t == 0) ? 0 : sh[t - 1];
#pragma unroll
    for (int k = 0; k < 4; k++) {
        int idx = t * 4 + k;
        if (idx < n) g_offset[idx] = base + loc[k];
    }
}

// One warp per row i: recompute predicate in the same j-order, ballot-compact
// into canonical slots, write edge_i / edge_j / weight / vec.
__global__ void fill_kernel(float* __restrict__ out, int n, int mp) {
    int warp = (blockIdx.x * blockDim.x + threadIdx.x) >> 5;
    int lane = threadIdx.x & 31;
    if (warp >= n) return;
    float4 pi = g_pos4[warp];
    int base = g_offset[warp];
    unsigned lt = (1u << lane) - 1u;
    float fi = (float)warp;
    for (int j0 = 0; j0 < n; j0 += 32) {
        int j = j0 + lane;
        float4 pj = g_pos4[j < n ? j : 0];
        float dx, dy, dz, d2;
        bool pred = pair_pred(pi, pj, warp, j, n, dx, dy, dz, d2);
        unsigned m = __ballot_sync(FULLMASK, pred);
        if (pred) {
            int slot = base + __popc(m & lt);
            if (slot < mp) {
                out[slot]          = fi;                 // edge_index[0]
                out[mp + slot]     = (float)j;           // edge_index[1]
                out[2 * mp + slot] = __fsqrt_rn(d2);     // edge_weight
                float* v = out + 3 * mp + 3 * slot;      // edge_vec (pair-major)
                v[0] = dx; v[1] = dy; v[2] = dz;
            }
        }
        base += __popc(m);
    }
}

extern "C" void kernel_launch(void* const* d_in, const int* in_sizes, int n_in,
                              void* d_out, int out_size) {
    const float* pos   = (const float*)d_in[0];
    const int*   batch = (const int*)d_in[1];
    float* out = (float*)d_out;

    int n  = in_sizes[1];          // batch element count == N
    if (n > N_MAX) n = N_MAX;
    int mp = out_size / 6;         // MAX_PAIRS

    pack_kernel<<<(n + 255) / 256, 256>>>(pos, batch, n);

    long long vec_elems = (6LL * mp + 3) / 4;
    init_kernel<<<(int)((vec_elems + 255) / 256), 256>>>(out, mp);

    int threads_total = n * 32;                   // one warp per row
    int blocks = (threads_total + 255) / 256;
    count_kernel<<<blocks, 256>>>(n);
    scan_kernel<<<1, 1024>>>(n);
    fill_kernel<<<blocks, 256>>>(out, n, mp);
}

// round 3
// speedup vs baseline: 1.6690x; 1.6690x over previous
#include <cuda_runtime.h>
#include <cstdint>

#define N_MAX 4096
#define W_MAX 128              // words per row (N_MAX/32)
#define FULLMASK 0xFFFFFFFFu

// Static scratch (allocations forbidden).
__device__ float4   g_pos4[N_MAX];
__device__ int      g_count[N_MAX];
__device__ int      g_offset[N_MAX];
__device__ unsigned g_mask[N_MAX * W_MAX];   // 2 MB ballot bitmap

// ---------------------------------------------------------------------------
// Pack pos (N,3)+batch into float4; pad rows [n, n_pad) with a sentinel whose
// batch bits can never match a real batch (predicate always false).
__global__ void pack_kernel(const float* __restrict__ pos,
                            const int* __restrict__ batch, int n, int n_pad) {
    int i = blockIdx.x * blockDim.x + threadIdx.x;
    if (i < n) {
        float4 p;
        p.x = pos[3 * i + 0];
        p.y = pos[3 * i + 1];
        p.z = pos[3 * i + 2];
        p.w = __int_as_float(batch[i]);
        g_pos4[i] = p;
    } else if (i < n_pad) {
        g_pos4[i] = make_float4(1e9f, 1e9f, 1e9f, __int_as_float(-2));
    }
}

// Initialize output: edge_index region = -1, weight/vec = 0. float4 stores.
__global__ void init_kernel(float* __restrict__ out, int mp) {
    long long idx = (long long)(blockIdx.x * (long long)blockDim.x + threadIdx.x) * 4;
    if (idx < 6LL * mp) {
        float v = (idx < 2LL * mp) ? -1.0f : 0.0f;
        *reinterpret_cast<float4*>(out + idx) = make_float4(v, v, v, v);
    }
}

// ---------------------------------------------------------------------------
// Pass A: one warp per row i. Evaluate all j in chunks of 32, persist the
// ballot word, accumulate the row count. Unrolled for MLP.
__global__ void mask_kernel(int n, int nw) {
    int warp = (blockIdx.x * blockDim.x + threadIdx.x) >> 5;
    int lane = threadIdx.x & 31;
    if (warp >= n) return;
    float4 pi = g_pos4[warp];
    int ibits = __float_as_int(pi.w);
    unsigned* mrow = g_mask + (size_t)warp * nw;
    int cnt = 0;
#pragma unroll 8
    for (int w = 0; w < nw; w++) {
        int j = w * 32 + lane;
        float4 pj = g_pos4[j];
        float dx = __fadd_rn(pi.x, -pj.x);
        float dy = __fadd_rn(pi.y, -pj.y);
        float dz = __fadd_rn(pi.z, -pj.z);
        float d2 = __fadd_rn(__fadd_rn(__fmul_rn(dx, dx), __fmul_rn(dy, dy)),
                             __fmul_rn(dz, dz));
        bool pred = (j != warp) & (ibits == __float_as_int(pj.w)) & (d2 < 25.0f);
        if (pred) pred = (__fsqrt_rn(d2) < 5.0f);   // rare borderline refinement
        unsigned m = __ballot_sync(FULLMASK, pred);
        if (lane == 0) mrow[w] = m;
        cnt += __popc(m);
    }
    if (lane == 0) g_count[warp] = cnt;
}

// ---------------------------------------------------------------------------
// Exclusive scan of 4096 counts: int4 per thread + shfl warp scans, 2 barriers.
__device__ __forceinline__ int warp_inc_scan(int v, int lane) {
#pragma unroll
    for (int off = 1; off < 32; off <<= 1) {
        int u = __shfl_up_sync(FULLMASK, v, off);
        if (lane >= off) v += u;
    }
    return v;
}

__global__ void scan_kernel() {
    __shared__ int wsum[32];
    int t = threadIdx.x;            // 1024 threads x 4 counts = 4096
    int lane = t & 31, w = t >> 5;
    int4 c = reinterpret_cast<int4*>(g_count)[t];
    int tot = c.x + c.y + c.z + c.w;
    int inc = warp_inc_scan(tot, lane);
    if (lane == 31) wsum[w] = inc;
    __syncthreads();
    if (w == 0) {
        int x = wsum[lane];
        x = warp_inc_scan(x, lane);
        wsum[lane] = x;
    }
    __syncthreads();
    int base = (w ? wsum[w - 1] : 0) + (inc - tot);   // exclusive prefix of thread
    int4 o;
    o.x = base;
    o.y = base + c.x;
    o.z = o.y + c.y;
    o.w = o.z + c.z;
    reinterpret_cast<int4*>(g_offset)[t] = o;
}

// ---------------------------------------------------------------------------
// Pass B: expand persisted masks. One warp per row; 32 mask words per step,
// warp-scan the popcounts for canonical slots, serial bit-loop per lane.
__global__ void fill_kernel(float* __restrict__ out, int n, int mp, int nw) {
    int row = (blockIdx.x * blockDim.x + threadIdx.x) >> 5;
    int lane = threadIdx.x & 31;
    if (row >= n) return;
    float4 pi = g_pos4[row];
    const unsigned* mrow = g_mask + (size_t)row * nw;
    int base = g_offset[row];
    float fi = (float)row;
    for (int w0 = 0; w0 < nw; w0 += 32) {
        unsigned m = mrow[w0 + lane];
        int pc = __popc(m);
        int inc = warp_inc_scan(pc, lane);
        int tot = __shfl_sync(FULLMASK, inc, 31);
        int slot = base + inc - pc;
        while (m) {
            int b = __ffs(m) - 1;
            m &= m - 1;
            int j = (w0 + lane) * 32 + b;
            float4 pj = g_pos4[j];
            float dx = __fadd_rn(pi.x, -pj.x);
            float dy = __fadd_rn(pi.y, -pj.y);
            float dz = __fadd_rn(pi.z, -pj.z);
            float d2 = __fadd_rn(__fadd_rn(__fmul_rn(dx, dx), __fmul_rn(dy, dy)),
                                 __fmul_rn(dz, dz));
            if (slot < mp) {
                out[slot]          = fi;
                out[mp + slot]     = (float)j;
                out[2 * mp + slot] = __fsqrt_rn(d2);
                float* v = out + 3 * mp + 3 * slot;
                v[0] = dx; v[1] = dy; v[2] = dz;
            }
            slot++;
        }
        base += tot;
    }
}

// ---------------------------------------------------------------------------
extern "C" void kernel_launch(void* const* d_in, const int* in_sizes, int n_in,
                              void* d_out, int out_size) {
    const float* pos   = (const float*)d_in[0];
    const int*   batch = (const int*)d_in[1];
    float* out = (float*)d_out;

    int n = in_sizes[1];
    if (n > N_MAX) n = N_MAX;
    int n_pad = (n + 31) & ~31;
    int nw = n_pad / 32;
    int mp = out_size / 6;

    pack_kernel<<<(n_pad + 255) / 256, 256>>>(pos, batch, n, n_pad);

    long long vec_elems = (6LL * mp + 3) / 4;
    init_kernel<<<(int)((vec_elems + 255) / 256), 256>>>(out, mp);

    int blocks = (n * 32 + 255) / 256;
    mask_kernel<<<blocks, 256>>>(n, nw);
    scan_kernel<<<1, 1024>>>();
    fill_kernel<<<blocks, 256>>>(out, n, mp, nw);
}